// round 11
// baseline (speedup 1.0000x reference)
#include <cuda_runtime.h>
#include <cuda_fp16.h>
#include <math.h>
#include <stdint.h>

#define D_MODEL 512
#define STATE_N 64
#define BATCH   4
#define SEQ     2048
#define M_ROWS  8192
#define NC      16
#define LCH     128
#define BD      2048
#define KCAT    1024           // 2 * 512 (fp16-split concatenated K)

// ------------------------- scratch (device globals) -----------------------
__device__ __align__(256) float  g_u   [M_ROWS*D_MODEL];
__device__ __align__(256) float  g_gate[M_ROWS*D_MODEL];
__device__ __align__(256) float2 g_S   [NC*BD*STATE_N];
__device__ __align__(256) float2 g_E   [NC*BD*STATE_N];
__device__ __align__(256) float  g_wr  [D_MODEL*STATE_N];
__device__ __align__(256) float  g_wi  [D_MODEL*STATE_N];
__device__ __align__(256) float  g_cb  [D_MODEL*STATE_N];
__device__ __align__(256) float  g_wLr [D_MODEL*STATE_N];
__device__ __align__(256) float  g_wLi [D_MODEL*STATE_N];
__device__ __align__(256) __half g_xcat  [M_ROWS*KCAT];
__device__ __align__(256) __half g_ycat  [M_ROWS*KCAT];
__device__ __align__(256) __half g_wincat[D_MODEL*KCAT];
__device__ __align__(256) __half g_wgcat [D_MODEL*KCAT];
__device__ __align__(256) __half g_wocat [D_MODEL*KCAT];

// ------------------------- f32x2 / ptx helpers ----------------------------
__device__ __forceinline__ unsigned long long ffma2(unsigned long long a,
                                                    unsigned long long b,
                                                    unsigned long long c) {
    unsigned long long d;
    asm("fma.rn.f32x2 %0, %1, %2, %3;" : "=l"(d) : "l"(a), "l"(b), "l"(c));
    return d;
}
__device__ __forceinline__ unsigned long long mul2(unsigned long long a,
                                                   unsigned long long b) {
    unsigned long long d;
    asm("mul.rn.f32x2 %0, %1, %2;" : "=l"(d) : "l"(a), "l"(b));
    return d;
}
__device__ __forceinline__ unsigned long long pk2(float x, float y) {
    unsigned long long r;
    asm("mov.b64 %0, {%1, %2};" : "=l"(r) : "r"(__float_as_uint(x)), "r"(__float_as_uint(y)));
    return r;
}
__device__ __forceinline__ float2 up2(unsigned long long v) {
    unsigned int lo, hi;
    asm("mov.b64 {%0, %1}, %2;" : "=r"(lo), "=r"(hi) : "l"(v));
    return make_float2(__uint_as_float(lo), __uint_as_float(hi));
}
__device__ __forceinline__ uint32_t smem_u32(const void* p) {
    uint32_t a;
    asm("{ .reg .u64 t; cvta.to.shared.u64 t, %1; cvt.u32.u64 %0, t; }" : "=r"(a) : "l"(p));
    return a;
}
__device__ __forceinline__ uint32_t sw128(uint32_t off) {
    return off ^ ((off >> 3) & 0x70);
}
__device__ __forceinline__ void ldmx4(uint32_t* r, uint32_t addr) {
    asm volatile("ldmatrix.sync.aligned.m8n8.x4.shared.b16 {%0,%1,%2,%3}, [%4];"
                 : "=r"(r[0]), "=r"(r[1]), "=r"(r[2]), "=r"(r[3]) : "r"(addr));
}
__device__ __forceinline__ void mma16816(float* d, const uint32_t* a,
                                         uint32_t b0, uint32_t b1) {
    asm volatile(
        "mma.sync.aligned.m16n8k16.row.col.f32.f16.f16.f32 "
        "{%0,%1,%2,%3},{%4,%5,%6,%7},{%8,%9},{%0,%1,%2,%3};"
        : "+f"(d[0]), "+f"(d[1]), "+f"(d[2]), "+f"(d[3])
        : "r"(a[0]), "r"(a[1]), "r"(a[2]), "r"(a[3]), "r"(b0), "r"(b1));
}
#define CP_ASYNC16(sm, gp) \
    asm volatile("cp.async.cg.shared.global [%0], [%1], 16;" :: "r"(sm), "l"(gp) : "memory")
#define CP_COMMIT() asm volatile("cp.async.commit_group;" ::: "memory")
#define CP_WAIT(n)  asm volatile("cp.async.wait_group %0;" :: "n"(n) : "memory")

// ------------------------- SSM parameter precompute -----------------------
__global__ void prep_kernel(const float* __restrict__ logAr,
                            const float* __restrict__ Aim,
                            const float* __restrict__ Bp,
                            const float* __restrict__ Cp,
                            const float* __restrict__ logdt) {
    int i = blockIdx.x * blockDim.x + threadIdx.x;
    if (i >= D_MODEL * STATE_N) return;
    int d = i >> 6;
    float dt  = expf(logdt[d]);
    float ar  = -expf(logAr[i]);
    float th  = dt * Aim[i];
    float mag = expf(dt * ar);
    float wrv = mag * cosf(th);
    float wiv = mag * sinf(th);
    g_wr[i] = wrv;
    g_wi[i] = wiv;
    g_cb[i] = Cp[i] * Bp[i] * dt;
    float xr = wrv, xi = wiv;
#pragma unroll
    for (int s = 0; s < 7; s++) {  // w^128
        float nr = xr * xr - xi * xi;
        float ni = 2.0f * xr * xi;
        xr = nr; xi = ni;
    }
    g_wLr[i] = xr;
    g_wLi[i] = xi;
}

// ------------------------- fp16 split conversions -------------------------
// Activation rows: [hi(512) | lo(512)] ; Weight rows: [hi(512) | hi(512)]
__global__ __launch_bounds__(256) void conv_split_x(const float* __restrict__ src) {
    const int i = blockIdx.x * 256 + threadIdx.x;
    const int m = i >> 8;
    const int c = (i & 255) * 2;
    float2 v = *(const float2*)(src + (size_t)m * 512 + c);
    __half h0 = __float2half(v.x);
    __half h1 = __float2half(v.y);
    __half l0 = __float2half(v.x - __half2float(h0));
    __half l1 = __float2half(v.y - __half2float(h1));
    __half2 hp = __halves2half2(h0, h1);
    __half2 lp = __halves2half2(l0, l1);
    __half* drow = g_xcat + (size_t)m * KCAT + c;
    *(__half2*)(drow)       = hp;
    *(__half2*)(drow + 512) = lp;
}
__global__ __launch_bounds__(256) void conv_split_w(const float* __restrict__ Win,
                                                    const float* __restrict__ Wg,
                                                    const float* __restrict__ Wo) {
    const int w = blockIdx.y;
    const float* src = (w == 0) ? Win : (w == 1) ? Wg : Wo;
    __half* dst = (w == 0) ? g_wincat : (w == 1) ? g_wgcat : g_wocat;
    const int i = blockIdx.x * 256 + threadIdx.x;
    const int m = i >> 8;
    const int c = (i & 255) * 2;
    float2 v = *(const float2*)(src + (size_t)m * 512 + c);
    __half2 hp = __halves2half2(__float2half(v.x), __float2half(v.y));
    __half* drow = dst + (size_t)m * KCAT + c;
    *(__half2*)(drow)       = hp;
    *(__half2*)(drow + 512) = hp;
}

// ------------------------- cp.async 2-stage fp16 GEMM (BM128/BN64/BK64) ---
// C[8192x512] = Acat[8192x1024] · Wcat[512x1024]^T  (fp16 in, fp32 acc)
// MODE 0: g_u = ...      MODE 1: g_gate = sigmoid(... + b_gate)
// MODE 2: out = x + g_gate * (...)
#define BM 128
#define BN 64
#define BK 64
#define NCH (KCAT/BK)       // 16
#define STG_BYTES 24576     // A 16KB + B 8KB
#define SMA(s) ((s)*STG_BYTES)
#define SMB(s) ((s)*STG_BYTES + 16384)

template<int MODE>
__global__ __launch_bounds__(256, 2) void gemm_mma(
    const float* __restrict__ x_ext,     // x (MODE 2 epilogue)
    float* __restrict__ Cout_ext,        // d_out (MODE 2)
    const float* __restrict__ bgate) {   // b_gate (MODE 1)
    __shared__ __align__(128) char smem[2 * STG_BYTES];   // 48KB
    const uint32_t sb = smem_u32(smem);
    const int tid  = threadIdx.x;
    const int wid  = tid >> 5, lane = tid & 31;
    const int wm   = wid & 3;          // 4 m-blocks of 32 rows
    const int wn   = wid >> 2;         // 2 n-blocks of 32 cols
    const int m0 = blockIdx.x * BM;
    const int n0 = blockIdx.y * BN;

    const __half* Acat = (MODE == 2) ? g_ycat : g_xcat;
    const __half* Wcat = (MODE == 0) ? g_wincat : (MODE == 1) ? g_wgcat : g_wocat;

    // ---- cp.async geometry (rows are 128 bytes = BK*2)
    // A: 128 rows, 2 thr/row, 4x16B each
    const int ra = tid >> 1;
    const int ca = (tid & 1) * 64;
    uint32_t stA[4];
#pragma unroll
    for (int i = 0; i < 4; i++) stA[i] = sw128((uint32_t)(ra * 128 + ca + i * 16));
    const char* Ag = (const char*)Acat + (size_t)(m0 + ra) * (KCAT * 2) + ca;
    // B: 64 rows, 4 thr/row, 2x16B each
    const int rb = tid >> 2;
    const int cbo = (tid & 3) * 32;
    uint32_t stB[2];
#pragma unroll
    for (int i = 0; i < 2; i++) stB[i] = sw128((uint32_t)(rb * 128 + cbo + i * 16));
    const char* Bg = (const char*)Wcat + (size_t)(n0 + rb) * (KCAT * 2) + cbo;

    // ---- ldmatrix per-lane base offsets (128B rows, SW128) — R8-validated
    const int grp = lane >> 3;
    const int l7  = lane & 7;
    const uint32_t a_base = (uint32_t)((wm * 32 + ((grp & 1) ? 8 : 0) + l7) * 128
                                       + ((grp >> 1) ? 16 : 0));
    const uint32_t b_base = (uint32_t)((wn * 32 + ((grp >> 1) ? 8 : 0) + l7) * 128
                                       + ((grp & 1) ? 16 : 0));

    float acc[2][4][4];
#pragma unroll
    for (int mf = 0; mf < 2; mf++)
#pragma unroll
        for (int nf = 0; nf < 4; nf++)
#pragma unroll
            for (int q = 0; q < 4; q++) acc[mf][nf][q] = 0.0f;

    // prologue: chunk 0 -> stage 0
#pragma unroll
    for (int i = 0; i < 4; i++) CP_ASYNC16(sb + SMA(0) + stA[i], Ag + i * 16);
#pragma unroll
    for (int i = 0; i < 2; i++) CP_ASYNC16(sb + SMB(0) + stB[i], Bg + i * 16);
    CP_COMMIT();

    int st = 0;
    for (int kc = 0; kc < NCH; kc++) {
        if (kc + 1 < NCH) {
            const char* An = Ag + (size_t)(kc + 1) * 128;
            const char* Bn = Bg + (size_t)(kc + 1) * 128;
#pragma unroll
            for (int i = 0; i < 4; i++) CP_ASYNC16(sb + SMA(st ^ 1) + stA[i], An + i * 16);
#pragma unroll
            for (int i = 0; i < 2; i++) CP_ASYNC16(sb + SMB(st ^ 1) + stB[i], Bn + i * 16);
            CP_COMMIT();
            CP_WAIT(1);
        } else {
            CP_WAIT(0);
        }
        __syncthreads();

        const uint32_t sa  = sb + SMA(st);
        const uint32_t sbB = sb + SMB(st);
#pragma unroll
        for (int s = 0; s < 4; s++) {        // 4 k-steps of 16
            uint32_t af[2][4];
#pragma unroll
            for (int mf = 0; mf < 2; mf++)
                ldmx4(af[mf], sa + sw128(a_base + mf * 2048 + s * 32));
            uint32_t bf[2][4];
#pragma unroll
            for (int nq = 0; nq < 2; nq++)
                ldmx4(bf[nq], sbB + sw128(b_base + nq * 2048 + s * 32));
#pragma unroll
            for (int mf = 0; mf < 2; mf++)
#pragma unroll
                for (int nq = 0; nq < 2; nq++) {
                    mma16816(acc[mf][nq * 2],     af[mf], bf[nq][0], bf[nq][1]);
                    mma16816(acc[mf][nq * 2 + 1], af[mf], bf[nq][2], bf[nq][3]);
                }
        }
        __syncthreads();
        st ^= 1;
    }

    // ---- epilogue
    const int rrow = lane >> 2;
    const int rcol = (lane & 3) * 2;
    float* Cbase = (MODE == 0) ? g_u : (MODE == 1) ? g_gate : Cout_ext;
#pragma unroll
    for (int mf = 0; mf < 2; mf++) {
        const int mrow = m0 + wm * 32 + mf * 16 + rrow;
#pragma unroll
        for (int nf = 0; nf < 4; nf++) {
            const int col = n0 + wn * 32 + nf * 8 + rcol;
            float2 v0 = make_float2(acc[mf][nf][0], acc[mf][nf][1]);
            float2 v1 = make_float2(acc[mf][nf][2], acc[mf][nf][3]);
            if (MODE == 1) {
                float2 bb = *(const float2*)(bgate + col);
                v0.x = __fdividef(1.0f, 1.0f + __expf(-(v0.x + bb.x)));
                v0.y = __fdividef(1.0f, 1.0f + __expf(-(v0.y + bb.y)));
                v1.x = __fdividef(1.0f, 1.0f + __expf(-(v1.x + bb.x)));
                v1.y = __fdividef(1.0f, 1.0f + __expf(-(v1.y + bb.y)));
            } else if (MODE == 2) {
                float2 x0 = *(const float2*)(x_ext + (size_t)mrow * 512 + col);
                float2 g0 = *(const float2*)(g_gate + (size_t)mrow * 512 + col);
                float2 x1 = *(const float2*)(x_ext + (size_t)(mrow + 8) * 512 + col);
                float2 g1 = *(const float2*)(g_gate + (size_t)(mrow + 8) * 512 + col);
                v0.x = fmaf(g0.x, v0.x, x0.x); v0.y = fmaf(g0.y, v0.y, x0.y);
                v1.x = fmaf(g1.x, v1.x, x1.x); v1.y = fmaf(g1.y, v1.y, x1.y);
            }
            *(float2*)(Cbase + (size_t)mrow * 512 + col)       = v0;
            *(float2*)(Cbase + (size_t)(mrow + 8) * 512 + col) = v1;
        }
    }
}

// ------------------------- scan phase 1 (f32x2-packed) --------------------
__global__ __launch_bounds__(256) void scan_phase1() {
    __shared__ float Us[LCH][32];
    const int tid  = threadIdx.x;
    const int dblk = blockIdx.x, c = blockIdx.y, b = blockIdx.z;
    const int dd = tid >> 3, j = tid & 7;
    const int d  = dblk * 32 + dd;

    const float* u = g_u + (size_t)(b * SEQ + c * LCH) * 512 + dblk * 32;
    for (int r = tid >> 5; r < LCH; r += 8)
        Us[r][tid & 31] = u[(size_t)r * 512 + (tid & 31)];
    __syncthreads();

    const int nbase = j * 8;
    unsigned long long wr2[4], wi2[4], nwi2[4], sr2[4], si2[4];
    {
        const float4* p = (const float4*)(g_wr + d * STATE_N + nbase);
        float4 t0 = p[0], t1 = p[1];
        wr2[0] = pk2(t0.x, t0.y); wr2[1] = pk2(t0.z, t0.w);
        wr2[2] = pk2(t1.x, t1.y); wr2[3] = pk2(t1.z, t1.w);
        p = (const float4*)(g_wi + d * STATE_N + nbase);
        t0 = p[0]; t1 = p[1];
        wi2[0] = pk2(t0.x, t0.y); wi2[1] = pk2(t0.z, t0.w);
        wi2[2] = pk2(t1.x, t1.y); wi2[3] = pk2(t1.z, t1.w);
        nwi2[0] = pk2(-t0.x, -t0.y); nwi2[1] = pk2(-t0.z, -t0.w);
        nwi2[2] = pk2(-t1.x, -t1.y); nwi2[3] = pk2(-t1.z, -t1.w);
    }
#pragma unroll
    for (int p = 0; p < 4; p++) { sr2[p] = 0ull; si2[p] = 0ull; }

#pragma unroll 4
    for (int t = 0; t < LCH; t++) {
        float ut = Us[t][dd];
        unsigned long long u2 = pk2(ut, ut);
#pragma unroll
        for (int p = 0; p < 4; p++) {
            unsigned long long mm = mul2(wi2[p], sr2[p]);
            unsigned long long tt = ffma2(nwi2[p], si2[p], u2);
            sr2[p] = ffma2(wr2[p], sr2[p], tt);
            si2[p] = ffma2(wr2[p], si2[p], mm);
        }
    }
    float2* Sp = g_S + ((size_t)(c * BD + b * D_MODEL + d)) * STATE_N + nbase;
#pragma unroll
    for (int p = 0; p < 4; p++) {
        float2 a = up2(sr2[p]), bb = up2(si2[p]);
        Sp[2 * p]     = make_float2(a.x, bb.x);
        Sp[2 * p + 1] = make_float2(a.y, bb.y);
    }
}

// ------------------------- scan phase 2 -----------------------------------
__global__ __launch_bounds__(256) void scan_phase2() {
    const int i  = blockIdx.x * blockDim.x + threadIdx.x;
    const int bd = i >> 6;
    const int n  = i & 63;
    const int d  = bd & (D_MODEL - 1);
    const float wLr = g_wLr[d * STATE_N + n];
    const float wLi = g_wLi[d * STATE_N + n];
    float er = 0.0f, ei = 0.0f;
#pragma unroll
    for (int c = 0; c < NC; c++) {
        const size_t idx = ((size_t)c * BD + bd) * STATE_N + n;
        g_E[idx] = make_float2(er, ei);
        float2 s = g_S[idx];
        float nr = fmaf(wLr, er, fmaf(-wLi, ei, s.x));
        float ni = fmaf(wLr, ei, fmaf(wLi, er, s.y));
        er = nr; ei = ni;
    }
}

// ------------------------- scan phase 3: scan + fused fp16 y-split --------
__global__ __launch_bounds__(256) void scan_phase3(const float* __restrict__ Dp) {
    __shared__ float Us[LCH][32];
    const int tid  = threadIdx.x;
    const int dblk = blockIdx.x, c = blockIdx.y, b = blockIdx.z;
    const int dd = tid >> 3, j = tid & 7;
    const int d  = dblk * 32 + dd;

    const float* u = g_u + (size_t)(b * SEQ + c * LCH) * 512 + dblk * 32;
    for (int r = tid >> 5; r < LCH; r += 8)
        Us[r][tid & 31] = u[(size_t)r * 512 + (tid & 31)];
    __syncthreads();

    const int nbase = j * 8;
    unsigned long long wr2[4], wi2[4], nwi2[4], cb2[4], sr2[4], si2[4];
    {
        const float4* p = (const float4*)(g_wr + d * STATE_N + nbase);
        float4 t0 = p[0], t1 = p[1];
        wr2[0] = pk2(t0.x, t0.y); wr2[1] = pk2(t0.z, t0.w);
        wr2[2] = pk2(t1.x, t1.y); wr2[3] = pk2(t1.z, t1.w);
        p = (const float4*)(g_wi + d * STATE_N + nbase);
        t0 = p[0]; t1 = p[1];
        wi2[0] = pk2(t0.x, t0.y); wi2[1] = pk2(t0.z, t0.w);
        wi2[2] = pk2(t1.x, t1.y); wi2[3] = pk2(t1.z, t1.w);
        nwi2[0] = pk2(-t0.x, -t0.y); nwi2[1] = pk2(-t0.z, -t0.w);
        nwi2[2] = pk2(-t1.x, -t1.y); nwi2[3] = pk2(-t1.z, -t1.w);
        p = (const float4*)(g_cb + d * STATE_N + nbase);
        t0 = p[0]; t1 = p[1];
        cb2[0] = pk2(t0.x, t0.y); cb2[1] = pk2(t0.z, t0.w);
        cb2[2] = pk2(t1.x, t1.y); cb2[3] = pk2(t1.z, t1.w);
    }
    {
        const float4* Ep = (const float4*)(g_E + ((size_t)(c * BD + b * D_MODEL + d)) * STATE_N + nbase);
#pragma unroll
        for (int p = 0; p < 4; p++) {
            float4 e = Ep[p];   // (sr0, si0, sr1, si1)
            sr2[p] = pk2(e.x, e.z);
            si2[p] = pk2(e.y, e.w);
        }
    }
    const float Dd = Dp[d];
    __half* ycat = g_ycat + (size_t)(b * SEQ + c * LCH) * KCAT + d;

#pragma unroll 4
    for (int t = 0; t < LCH; t++) {
        float ut = Us[t][dd];
        unsigned long long u2 = pk2(ut, ut);
        unsigned long long acc2 = 0ull;
#pragma unroll
        for (int p = 0; p < 4; p++) {
            unsigned long long mm = mul2(wi2[p], sr2[p]);
            unsigned long long tt = ffma2(nwi2[p], si2[p], u2);
            sr2[p] = ffma2(wr2[p], sr2[p], tt);
            si2[p] = ffma2(wr2[p], si2[p], mm);
            acc2   = ffma2(cb2[p], sr2[p], acc2);
        }
        float2 ap = up2(acc2);
        float accv = ap.x + ap.y;
        accv += __shfl_xor_sync(0xffffffffu, accv, 1, 8);
        accv += __shfl_xor_sync(0xffffffffu, accv, 2, 8);
        accv += __shfl_xor_sync(0xffffffffu, accv, 4, 8);
        if (j == 0) {
            float v = fmaf(Dd, ut, accv);
            __half h = __float2half(v);
            __half l = __float2half(v - __half2float(h));
            ycat[(size_t)t * KCAT]       = h;
            ycat[(size_t)t * KCAT + 512] = l;
        }
    }
}

// ------------------------- launch ----------------------------------------
extern "C" void kernel_launch(void* const* d_in, const int* in_sizes, int n_in,
                              void* d_out, int out_size) {
    const float* x      = (const float*)d_in[0];
    const float* logAr  = (const float*)d_in[1];
    const float* Aim    = (const float*)d_in[2];
    const float* Bp_    = (const float*)d_in[3];
    const float* Cp_    = (const float*)d_in[4];
    const float* Dp_    = (const float*)d_in[5];
    const float* logdt  = (const float*)d_in[6];
    const float* W_in   = (const float*)d_in[7];
    const float* W_out  = (const float*)d_in[8];
    const float* W_gate = (const float*)d_in[9];
    const float* b_gate = (const float*)d_in[10];
    float* out = (float*)d_out;

    prep_kernel<<<(D_MODEL * STATE_N + 255) / 256, 256>>>(logAr, Aim, Bp_, Cp_, logdt);
    conv_split_x<<<M_ROWS, 256>>>(x);
    conv_split_w<<<dim3(D_MODEL, 3), 256>>>(W_in, W_gate, W_out);
    gemm_mma<0><<<dim3(M_ROWS / BM, D_MODEL / BN), 256>>>(nullptr, nullptr, nullptr);
    gemm_mma<1><<<dim3(M_ROWS / BM, D_MODEL / BN), 256>>>(nullptr, nullptr, b_gate);
    scan_phase1<<<dim3(D_MODEL / 32, NC, BATCH), 256>>>();
    scan_phase2<<<(BD * STATE_N) / 256, 256>>>();
    scan_phase3<<<dim3(D_MODEL / 32, NC, BATCH), 256>>>(Dp_);
    gemm_mma<2><<<dim3(M_ROWS / BM, D_MODEL / BN), 256>>>(x, out, nullptr);
}

// round 12
// speedup vs baseline: 1.0859x; 1.0859x over previous
#include <cuda_runtime.h>
#include <cuda_fp16.h>
#include <math.h>
#include <stdint.h>

#define D_MODEL 512
#define STATE_N 64
#define BATCH   4
#define SEQ     2048
#define M_ROWS  8192
#define NC      16
#define LCH     128
#define BD      2048
#define KCAT    1024           // 2 * 512 (fp16-split concatenated K)

// ------------------------- scratch (device globals) -----------------------
__device__ __align__(256) float  g_u   [M_ROWS*D_MODEL];
__device__ __align__(256) float  g_gate[M_ROWS*D_MODEL];
__device__ __align__(256) float2 g_S   [NC*BD*STATE_N];
__device__ __align__(256) float2 g_E   [NC*BD*STATE_N];
__device__ __align__(256) float  g_wr  [D_MODEL*STATE_N];
__device__ __align__(256) float  g_wi  [D_MODEL*STATE_N];
__device__ __align__(256) float  g_cb  [D_MODEL*STATE_N];
__device__ __align__(256) float  g_wLr [D_MODEL*STATE_N];
__device__ __align__(256) float  g_wLi [D_MODEL*STATE_N];
__device__ __align__(256) __half g_xcat  [M_ROWS*KCAT];
__device__ __align__(256) __half g_ycat  [M_ROWS*KCAT];
__device__ __align__(256) __half g_wincat[D_MODEL*KCAT];
__device__ __align__(256) __half g_wgcat [D_MODEL*KCAT];
__device__ __align__(256) __half g_wocat [D_MODEL*KCAT];

// ------------------------- f32x2 / ptx helpers ----------------------------
__device__ __forceinline__ unsigned long long ffma2(unsigned long long a,
                                                    unsigned long long b,
                                                    unsigned long long c) {
    unsigned long long d;
    asm("fma.rn.f32x2 %0, %1, %2, %3;" : "=l"(d) : "l"(a), "l"(b), "l"(c));
    return d;
}
__device__ __forceinline__ unsigned long long mul2(unsigned long long a,
                                                   unsigned long long b) {
    unsigned long long d;
    asm("mul.rn.f32x2 %0, %1, %2;" : "=l"(d) : "l"(a), "l"(b));
    return d;
}
__device__ __forceinline__ unsigned long long pk2(float x, float y) {
    unsigned long long r;
    asm("mov.b64 %0, {%1, %2};" : "=l"(r) : "r"(__float_as_uint(x)), "r"(__float_as_uint(y)));
    return r;
}
__device__ __forceinline__ float2 up2(unsigned long long v) {
    unsigned int lo, hi;
    asm("mov.b64 {%0, %1}, %2;" : "=r"(lo), "=r"(hi) : "l"(v));
    return make_float2(__uint_as_float(lo), __uint_as_float(hi));
}
__device__ __forceinline__ uint32_t smem_u32(const void* p) {
    uint32_t a;
    asm("{ .reg .u64 t; cvta.to.shared.u64 t, %1; cvt.u32.u64 %0, t; }" : "=r"(a) : "l"(p));
    return a;
}
__device__ __forceinline__ uint32_t sw128(uint32_t off) {
    return off ^ ((off >> 3) & 0x70);
}
__device__ __forceinline__ void ldmx4(uint32_t* r, uint32_t addr) {
    asm volatile("ldmatrix.sync.aligned.m8n8.x4.shared.b16 {%0,%1,%2,%3}, [%4];"
                 : "=r"(r[0]), "=r"(r[1]), "=r"(r[2]), "=r"(r[3]) : "r"(addr));
}
__device__ __forceinline__ void mma16816(float* d, const uint32_t* a,
                                         uint32_t b0, uint32_t b1) {
    asm volatile(
        "mma.sync.aligned.m16n8k16.row.col.f32.f16.f16.f32 "
        "{%0,%1,%2,%3},{%4,%5,%6,%7},{%8,%9},{%0,%1,%2,%3};"
        : "+f"(d[0]), "+f"(d[1]), "+f"(d[2]), "+f"(d[3])
        : "r"(a[0]), "r"(a[1]), "r"(a[2]), "r"(a[3]), "r"(b0), "r"(b1));
}

// ------------------------- SSM parameter precompute -----------------------
__global__ void prep_kernel(const float* __restrict__ logAr,
                            const float* __restrict__ Aim,
                            const float* __restrict__ Bp,
                            const float* __restrict__ Cp,
                            const float* __restrict__ logdt) {
    int i = blockIdx.x * blockDim.x + threadIdx.x;
    if (i >= D_MODEL * STATE_N) return;
    int d = i >> 6;
    float dt  = expf(logdt[d]);
    float ar  = -expf(logAr[i]);
    float th  = dt * Aim[i];
    float mag = expf(dt * ar);
    float wrv = mag * cosf(th);
    float wiv = mag * sinf(th);
    g_wr[i] = wrv;
    g_wi[i] = wiv;
    g_cb[i] = Cp[i] * Bp[i] * dt;
    float xr = wrv, xi = wiv;
#pragma unroll
    for (int s = 0; s < 7; s++) {  // w^128
        float nr = xr * xr - xi * xi;
        float ni = 2.0f * xr * xi;
        xr = nr; xi = ni;
    }
    g_wLr[i] = xr;
    g_wLi[i] = xi;
}

// ------------------------- fp16 split conversions -------------------------
// Activation rows: [hi(512) | lo(512)] ; Weight rows: [hi(512) | hi(512)]
__global__ __launch_bounds__(256) void conv_split_x(const float* __restrict__ src) {
    const int i = blockIdx.x * 256 + threadIdx.x;
    const int m = i >> 8;
    const int c = (i & 255) * 2;
    float2 v = *(const float2*)(src + (size_t)m * 512 + c);
    __half h0 = __float2half(v.x);
    __half h1 = __float2half(v.y);
    __half l0 = __float2half(v.x - __half2float(h0));
    __half l1 = __float2half(v.y - __half2float(h1));
    __half2 hp = __halves2half2(h0, h1);
    __half2 lp = __halves2half2(l0, l1);
    __half* drow = g_xcat + (size_t)m * KCAT + c;
    *(__half2*)(drow)       = hp;
    *(__half2*)(drow + 512) = lp;
}
__global__ __launch_bounds__(256) void conv_split_w(const float* __restrict__ Win,
                                                    const float* __restrict__ Wg,
                                                    const float* __restrict__ Wo) {
    const int w = blockIdx.y;
    const float* src = (w == 0) ? Win : (w == 1) ? Wg : Wo;
    __half* dst = (w == 0) ? g_wincat : (w == 1) ? g_wgcat : g_wocat;
    const int i = blockIdx.x * 256 + threadIdx.x;
    const int m = i >> 8;
    const int c = (i & 255) * 2;
    float2 v = *(const float2*)(src + (size_t)m * 512 + c);
    __half2 hp = __halves2half2(__float2half(v.x), __float2half(v.y));
    __half* drow = dst + (size_t)m * KCAT + c;
    *(__half2*)(drow)       = hp;
    *(__half2*)(drow + 512) = hp;
}

// ------------------------- ldmatrix + mma.sync fp16 GEMM (R8 mainloop) ----
// C[8192x512] = Acat[8192x1024] · Wcat[512x1024]^T  (fp16 in, fp32 acc)
// FUSED=1: blockIdx.z==0 -> g_u = x@W_in^T ; z==1 -> g_gate = sigmoid(..+b)
// FUSED=0: out = x + g_gate * (g_ycat@W_out^T)
#define BM 128
#define BN 128
#define BK 64
#define NCH (KCAT/BK)   // 16
#define SM_A 1024
#define SM_B 17408
#define GEMM_SMEM 33792

template<int FUSED01>
__global__ __launch_bounds__(256) void gemm_mma(
    const float* __restrict__ x_ext,     // x (FUSED=0 epilogue)
    float* __restrict__ Cout_ext,        // d_out (FUSED=0)
    const float* __restrict__ bgate) {   // b_gate (FUSED=1, z=1)
    __shared__ __align__(128) char smem[GEMM_SMEM];
    const uint32_t sb = smem_u32(smem);
    const int tid  = threadIdx.x;
    const int wid  = tid >> 5, lane = tid & 31;
    const int wm   = wid & 3;          // 4 m-blocks of 32 rows
    const int wn   = wid >> 2;         // 2 n-blocks of 64 cols
    const int m0 = blockIdx.x * BM;
    const int n0 = blockIdx.y * BN;
    const int bz = FUSED01 ? blockIdx.z : 0;   // 0: in-proj, 1: gate-proj

    const __half* Acat = FUSED01 ? g_xcat : g_ycat;
    const __half* Wcat = FUSED01 ? (bz ? g_wgcat : g_wincat) : g_wocat;

    if (FUSED01 && bz && tid < BN) ((float*)smem)[tid] = bgate[n0 + tid];

    // ---- global->reg prefetch geometry (4 x 16B per thread per tile)
    const int r_base = tid >> 3;            // 0..31
    const int cb_off = (tid & 7) * 16;      // byte col within 128B row
    uint32_t sw_st[4];
#pragma unroll
    for (int i = 0; i < 4; i++)
        sw_st[i] = sw128((uint32_t)((r_base + i * 32) * 128 + cb_off));
    const char* Abase = (const char*)(Acat + (size_t)(m0 + r_base) * KCAT) + cb_off;
    const char* Bbase = (const char*)(Wcat + (size_t)(n0 + r_base) * KCAT) + cb_off;
    const size_t rstep = (size_t)32 * KCAT * 2;

    uint4 aR[4], bR[4];
#pragma unroll
    for (int i = 0; i < 4; i++) {
        aR[i] = *(const uint4*)(Abase + i * rstep);
        bR[i] = *(const uint4*)(Bbase + i * rstep);
    }

    // ---- ldmatrix per-lane base offsets
    const int grp = lane >> 3;
    const int l7  = lane & 7;
    const uint32_t a_base = (uint32_t)((wm * 32 + ((grp & 1) ? 8 : 0) + l7) * 128
                                       + ((grp >> 1) ? 16 : 0));
    const uint32_t b_base = (uint32_t)((wn * 64 + ((grp >> 1) ? 8 : 0) + l7) * 128
                                       + ((grp & 1) ? 16 : 0));

    float acc[2][8][4];
#pragma unroll
    for (int mf = 0; mf < 2; mf++)
#pragma unroll
        for (int nf = 0; nf < 8; nf++)
#pragma unroll
            for (int q = 0; q < 4; q++) acc[mf][nf][q] = 0.0f;

    for (int kc = 0; kc < NCH; kc++) {
        if (kc) __syncthreads();
#pragma unroll
        for (int i = 0; i < 4; i++) {
            asm volatile("st.shared.v4.b32 [%0], {%1,%2,%3,%4};"
                         :: "r"(sb + SM_A + sw_st[i]),
                            "r"(aR[i].x), "r"(aR[i].y), "r"(aR[i].z), "r"(aR[i].w) : "memory");
            asm volatile("st.shared.v4.b32 [%0], {%1,%2,%3,%4};"
                         :: "r"(sb + SM_B + sw_st[i]),
                            "r"(bR[i].x), "r"(bR[i].y), "r"(bR[i].z), "r"(bR[i].w) : "memory");
        }
        __syncthreads();
        if (kc + 1 < NCH) {   // prefetch next chunk during compute
            const char* An = Abase + (size_t)(kc + 1) * (BK * 2);
            const char* Bn = Bbase + (size_t)(kc + 1) * (BK * 2);
#pragma unroll
            for (int i = 0; i < 4; i++) {
                aR[i] = *(const uint4*)(An + i * rstep);
                bR[i] = *(const uint4*)(Bn + i * rstep);
            }
        }
#pragma unroll
        for (int s = 0; s < 4; s++) {      // 4 k-steps of 16
            uint32_t af[2][4];
#pragma unroll
            for (int mf = 0; mf < 2; mf++)
                ldmx4(af[mf], sb + SM_A + sw128(a_base + mf * 2048 + s * 32));
            uint32_t bf[4][4];
#pragma unroll
            for (int nq = 0; nq < 4; nq++)
                ldmx4(bf[nq], sb + SM_B + sw128(b_base + nq * 2048 + s * 32));
#pragma unroll
            for (int mf = 0; mf < 2; mf++)
#pragma unroll
                for (int nq = 0; nq < 4; nq++) {
                    mma16816(acc[mf][nq * 2],     af[mf], bf[nq][0], bf[nq][1]);
                    mma16816(acc[mf][nq * 2 + 1], af[mf], bf[nq][2], bf[nq][3]);
                }
        }
    }

    // ---- epilogue
    const int rrow = lane >> 2;
    const int rcol = (lane & 3) * 2;
    float* Cbase = FUSED01 ? (bz ? g_gate : g_u) : Cout_ext;
#pragma unroll
    for (int mf = 0; mf < 2; mf++) {
        const int mrow = m0 + wm * 32 + mf * 16 + rrow;
#pragma unroll
        for (int nf = 0; nf < 8; nf++) {
            const int ncl = wn * 64 + nf * 8 + rcol;   // 0..127 within tile
            const int col = n0 + ncl;
            float2 v0 = make_float2(acc[mf][nf][0], acc[mf][nf][1]);
            float2 v1 = make_float2(acc[mf][nf][2], acc[mf][nf][3]);
            if (FUSED01) {
                if (bz) {
                    float2 bb = *(const float2*)((const float*)smem + ncl);
                    v0.x = __fdividef(1.0f, 1.0f + __expf(-(v0.x + bb.x)));
                    v0.y = __fdividef(1.0f, 1.0f + __expf(-(v0.y + bb.y)));
                    v1.x = __fdividef(1.0f, 1.0f + __expf(-(v1.x + bb.x)));
                    v1.y = __fdividef(1.0f, 1.0f + __expf(-(v1.y + bb.y)));
                }
            } else {
                float2 x0 = *(const float2*)(x_ext + (size_t)mrow * 512 + col);
                float2 g0 = *(const float2*)(g_gate + (size_t)mrow * 512 + col);
                float2 x1 = *(const float2*)(x_ext + (size_t)(mrow + 8) * 512 + col);
                float2 g1 = *(const float2*)(g_gate + (size_t)(mrow + 8) * 512 + col);
                v0.x = fmaf(g0.x, v0.x, x0.x); v0.y = fmaf(g0.y, v0.y, x0.y);
                v1.x = fmaf(g1.x, v1.x, x1.x); v1.y = fmaf(g1.y, v1.y, x1.y);
            }
            *(float2*)(Cbase + (size_t)mrow * 512 + col)       = v0;
            *(float2*)(Cbase + (size_t)(mrow + 8) * 512 + col) = v1;
        }
    }
}

// ------------------------- scan phase 1 (f32x2-packed) --------------------
__global__ __launch_bounds__(256) void scan_phase1() {
    __shared__ float Us[LCH][32];
    const int tid  = threadIdx.x;
    const int dblk = blockIdx.x, c = blockIdx.y, b = blockIdx.z;
    const int dd = tid >> 3, j = tid & 7;
    const int d  = dblk * 32 + dd;

    const float* u = g_u + (size_t)(b * SEQ + c * LCH) * 512 + dblk * 32;
    for (int r = tid >> 5; r < LCH; r += 8)
        Us[r][tid & 31] = u[(size_t)r * 512 + (tid & 31)];
    __syncthreads();

    const int nbase = j * 8;
    unsigned long long wr2[4], wi2[4], nwi2[4], sr2[4], si2[4];
    {
        const float4* p = (const float4*)(g_wr + d * STATE_N + nbase);
        float4 t0 = p[0], t1 = p[1];
        wr2[0] = pk2(t0.x, t0.y); wr2[1] = pk2(t0.z, t0.w);
        wr2[2] = pk2(t1.x, t1.y); wr2[3] = pk2(t1.z, t1.w);
        p = (const float4*)(g_wi + d * STATE_N + nbase);
        t0 = p[0]; t1 = p[1];
        wi2[0] = pk2(t0.x, t0.y); wi2[1] = pk2(t0.z, t0.w);
        wi2[2] = pk2(t1.x, t1.y); wi2[3] = pk2(t1.z, t1.w);
        nwi2[0] = pk2(-t0.x, -t0.y); nwi2[1] = pk2(-t0.z, -t0.w);
        nwi2[2] = pk2(-t1.x, -t1.y); nwi2[3] = pk2(-t1.z, -t1.w);
    }
#pragma unroll
    for (int p = 0; p < 4; p++) { sr2[p] = 0ull; si2[p] = 0ull; }

#pragma unroll 4
    for (int t = 0; t < LCH; t++) {
        float ut = Us[t][dd];
        unsigned long long u2 = pk2(ut, ut);
#pragma unroll
        for (int p = 0; p < 4; p++) {
            unsigned long long mm = mul2(wi2[p], sr2[p]);
            unsigned long long tt = ffma2(nwi2[p], si2[p], u2);
            sr2[p] = ffma2(wr2[p], sr2[p], tt);
            si2[p] = ffma2(wr2[p], si2[p], mm);
        }
    }
    float2* Sp = g_S + ((size_t)(c * BD + b * D_MODEL + d)) * STATE_N + nbase;
#pragma unroll
    for (int p = 0; p < 4; p++) {
        float2 a = up2(sr2[p]), bb = up2(si2[p]);
        Sp[2 * p]     = make_float2(a.x, bb.x);
        Sp[2 * p + 1] = make_float2(a.y, bb.y);
    }
}

// ------------------------- scan phase 2 -----------------------------------
__global__ __launch_bounds__(256) void scan_phase2() {
    const int i  = blockIdx.x * blockDim.x + threadIdx.x;
    const int bd = i >> 6;
    const int n  = i & 63;
    const int d  = bd & (D_MODEL - 1);
    const float wLr = g_wLr[d * STATE_N + n];
    const float wLi = g_wLi[d * STATE_N + n];
    float er = 0.0f, ei = 0.0f;
#pragma unroll
    for (int c = 0; c < NC; c++) {
        const size_t idx = ((size_t)c * BD + bd) * STATE_N + n;
        g_E[idx] = make_float2(er, ei);
        float2 s = g_S[idx];
        float nr = fmaf(wLr, er, fmaf(-wLi, ei, s.x));
        float ni = fmaf(wLr, ei, fmaf(wLi, er, s.y));
        er = nr; ei = ni;
    }
}

// ------------------------- scan phase 3: scan + fused fp16 y-split --------
__global__ __launch_bounds__(256) void scan_phase3(const float* __restrict__ Dp) {
    __shared__ float Us[LCH][32];
    const int tid  = threadIdx.x;
    const int dblk = blockIdx.x, c = blockIdx.y, b = blockIdx.z;
    const int dd = tid >> 3, j = tid & 7;
    const int d  = dblk * 32 + dd;

    const float* u = g_u + (size_t)(b * SEQ + c * LCH) * 512 + dblk * 32;
    for (int r = tid >> 5; r < LCH; r += 8)
        Us[r][tid & 31] = u[(size_t)r * 512 + (tid & 31)];
    __syncthreads();

    const int nbase = j * 8;
    unsigned long long wr2[4], wi2[4], nwi2[4], cb2[4], sr2[4], si2[4];
    {
        const float4* p = (const float4*)(g_wr + d * STATE_N + nbase);
        float4 t0 = p[0], t1 = p[1];
        wr2[0] = pk2(t0.x, t0.y); wr2[1] = pk2(t0.z, t0.w);
        wr2[2] = pk2(t1.x, t1.y); wr2[3] = pk2(t1.z, t1.w);
        p = (const float4*)(g_wi + d * STATE_N + nbase);
        t0 = p[0]; t1 = p[1];
        wi2[0] = pk2(t0.x, t0.y); wi2[1] = pk2(t0.z, t0.w);
        wi2[2] = pk2(t1.x, t1.y); wi2[3] = pk2(t1.z, t1.w);
        nwi2[0] = pk2(-t0.x, -t0.y); nwi2[1] = pk2(-t0.z, -t0.w);
        nwi2[2] = pk2(-t1.x, -t1.y); nwi2[3] = pk2(-t1.z, -t1.w);
        p = (const float4*)(g_cb + d * STATE_N + nbase);
        t0 = p[0]; t1 = p[1];
        cb2[0] = pk2(t0.x, t0.y); cb2[1] = pk2(t0.z, t0.w);
        cb2[2] = pk2(t1.x, t1.y); cb2[3] = pk2(t1.z, t1.w);
    }
    {
        const float4* Ep = (const float4*)(g_E + ((size_t)(c * BD + b * D_MODEL + d)) * STATE_N + nbase);
#pragma unroll
        for (int p = 0; p < 4; p++) {
            float4 e = Ep[p];   // (sr0, si0, sr1, si1)
            sr2[p] = pk2(e.x, e.z);
            si2[p] = pk2(e.y, e.w);
        }
    }
    const float Dd = Dp[d];
    __half* ycat = g_ycat + (size_t)(b * SEQ + c * LCH) * KCAT + d;

#pragma unroll 4
    for (int t = 0; t < LCH; t++) {
        float ut = Us[t][dd];
        unsigned long long u2 = pk2(ut, ut);
        unsigned long long acc2 = 0ull;
#pragma unroll
        for (int p = 0; p < 4; p++) {
            unsigned long long mm = mul2(wi2[p], sr2[p]);
            unsigned long long tt = ffma2(nwi2[p], si2[p], u2);
            sr2[p] = ffma2(wr2[p], sr2[p], tt);
            si2[p] = ffma2(wr2[p], si2[p], mm);
            acc2   = ffma2(cb2[p], sr2[p], acc2);
        }
        float2 ap = up2(acc2);
        float accv = ap.x + ap.y;
        accv += __shfl_xor_sync(0xffffffffu, accv, 1, 8);
        accv += __shfl_xor_sync(0xffffffffu, accv, 2, 8);
        accv += __shfl_xor_sync(0xffffffffu, accv, 4, 8);
        if (j == 0) {
            float v = fmaf(Dd, ut, accv);
            __half h = __float2half(v);
            __half l = __float2half(v - __half2float(h));
            ycat[(size_t)t * KCAT]       = h;
            ycat[(size_t)t * KCAT + 512] = l;
        }
    }
}

// ------------------------- launch ----------------------------------------
extern "C" void kernel_launch(void* const* d_in, const int* in_sizes, int n_in,
                              void* d_out, int out_size) {
    const float* x      = (const float*)d_in[0];
    const float* logAr  = (const float*)d_in[1];
    const float* Aim    = (const float*)d_in[2];
    const float* Bp_    = (const float*)d_in[3];
    const float* Cp_    = (const float*)d_in[4];
    const float* Dp_    = (const float*)d_in[5];
    const float* logdt  = (const float*)d_in[6];
    const float* W_in   = (const float*)d_in[7];
    const float* W_out  = (const float*)d_in[8];
    const float* W_gate = (const float*)d_in[9];
    const float* b_gate = (const float*)d_in[10];
    float* out = (float*)d_out;

    prep_kernel<<<(D_MODEL * STATE_N + 255) / 256, 256>>>(logAr, Aim, Bp_, Cp_, logdt);
    conv_split_x<<<M_ROWS, 256>>>(x);
    conv_split_w<<<dim3(D_MODEL, 3), 256>>>(W_in, W_gate, W_out);
    gemm_mma<1><<<dim3(M_ROWS / BM, D_MODEL / BN, 2), 256>>>(nullptr, nullptr, b_gate);
    scan_phase1<<<dim3(D_MODEL / 32, NC, BATCH), 256>>>();
    scan_phase2<<<(BD * STATE_N) / 256, 256>>>();
    scan_phase3<<<dim3(D_MODEL / 32, NC, BATCH), 256>>>(Dp_);
    gemm_mma<0><<<dim3(M_ROWS / BM, D_MODEL / BN, 1), 256>>>(x, out, nullptr);
}

// round 13
// speedup vs baseline: 1.3508x; 1.2440x over previous
#include <cuda_runtime.h>
#include <cuda_fp16.h>
#include <math.h>
#include <stdint.h>

#define D_MODEL 512
#define STATE_N 64
#define BATCH   4
#define SEQ     2048
#define M_ROWS  8192
#define NC      16
#define LCH     128
#define BD      2048
#define KCAT    512            // plain fp16, no split

// ------------------------- scratch (device globals) -----------------------
__device__ __align__(256) float  g_u   [M_ROWS*D_MODEL];
__device__ __align__(256) float  g_gate[M_ROWS*D_MODEL];
__device__ __align__(256) float2 g_S   [NC*BD*STATE_N];
__device__ __align__(256) float2 g_E   [NC*BD*STATE_N];
__device__ __align__(256) float  g_wr  [D_MODEL*STATE_N];
__device__ __align__(256) float  g_wi  [D_MODEL*STATE_N];
__device__ __align__(256) float  g_cb  [D_MODEL*STATE_N];
__device__ __align__(256) float  g_wLr [D_MODEL*STATE_N];
__device__ __align__(256) float  g_wLi [D_MODEL*STATE_N];
__device__ __align__(256) __half g_xcat  [M_ROWS*KCAT];
__device__ __align__(256) __half g_ycat  [M_ROWS*KCAT];
__device__ __align__(256) __half g_wincat[D_MODEL*KCAT];
__device__ __align__(256) __half g_wgcat [D_MODEL*KCAT];
__device__ __align__(256) __half g_wocat [D_MODEL*KCAT];

// ------------------------- f32x2 / ptx helpers ----------------------------
__device__ __forceinline__ unsigned long long ffma2(unsigned long long a,
                                                    unsigned long long b,
                                                    unsigned long long c) {
    unsigned long long d;
    asm("fma.rn.f32x2 %0, %1, %2, %3;" : "=l"(d) : "l"(a), "l"(b), "l"(c));
    return d;
}
__device__ __forceinline__ unsigned long long mul2(unsigned long long a,
                                                   unsigned long long b) {
    unsigned long long d;
    asm("mul.rn.f32x2 %0, %1, %2;" : "=l"(d) : "l"(a), "l"(b));
    return d;
}
__device__ __forceinline__ unsigned long long pk2(float x, float y) {
    unsigned long long r;
    asm("mov.b64 %0, {%1, %2};" : "=l"(r) : "r"(__float_as_uint(x)), "r"(__float_as_uint(y)));
    return r;
}
__device__ __forceinline__ float2 up2(unsigned long long v) {
    unsigned int lo, hi;
    asm("mov.b64 {%0, %1}, %2;" : "=r"(lo), "=r"(hi) : "l"(v));
    return make_float2(__uint_as_float(lo), __uint_as_float(hi));
}
__device__ __forceinline__ uint32_t smem_u32(const void* p) {
    uint32_t a;
    asm("{ .reg .u64 t; cvta.to.shared.u64 t, %1; cvt.u32.u64 %0, t; }" : "=r"(a) : "l"(p));
    return a;
}
__device__ __forceinline__ uint32_t sw128(uint32_t off) {
    return off ^ ((off >> 3) & 0x70);
}
__device__ __forceinline__ void ldmx4(uint32_t* r, uint32_t addr) {
    asm volatile("ldmatrix.sync.aligned.m8n8.x4.shared.b16 {%0,%1,%2,%3}, [%4];"
                 : "=r"(r[0]), "=r"(r[1]), "=r"(r[2]), "=r"(r[3]) : "r"(addr));
}
__device__ __forceinline__ void mma16816(float* d, const uint32_t* a,
                                         uint32_t b0, uint32_t b1) {
    asm volatile(
        "mma.sync.aligned.m16n8k16.row.col.f32.f16.f16.f32 "
        "{%0,%1,%2,%3},{%4,%5,%6,%7},{%8,%9},{%0,%1,%2,%3};"
        : "+f"(d[0]), "+f"(d[1]), "+f"(d[2]), "+f"(d[3])
        : "r"(a[0]), "r"(a[1]), "r"(a[2]), "r"(a[3]), "r"(b0), "r"(b1));
}

// ------------------------- SSM parameter precompute -----------------------
__global__ void prep_kernel(const float* __restrict__ logAr,
                            const float* __restrict__ Aim,
                            const float* __restrict__ Bp,
                            const float* __restrict__ Cp,
                            const float* __restrict__ logdt) {
    int i = blockIdx.x * blockDim.x + threadIdx.x;
    if (i >= D_MODEL * STATE_N) return;
    int d = i >> 6;
    float dt  = expf(logdt[d]);
    float ar  = -expf(logAr[i]);
    float th  = dt * Aim[i];
    float mag = expf(dt * ar);
    float wrv = mag * cosf(th);
    float wiv = mag * sinf(th);
    g_wr[i] = wrv;
    g_wi[i] = wiv;
    g_cb[i] = Cp[i] * Bp[i] * dt;
    float xr = wrv, xi = wiv;
#pragma unroll
    for (int s = 0; s < 7; s++) {  // w^128
        float nr = xr * xr - xi * xi;
        float ni = 2.0f * xr * xi;
        xr = nr; xi = ni;
    }
    g_wLr[i] = xr;
    g_wLi[i] = xi;
}

// ------------------------- fp16 conversions -------------------------------
__global__ __launch_bounds__(256) void conv_x(const float* __restrict__ src) {
    const int i = blockIdx.x * 256 + threadIdx.x;
    const int m = i >> 8;
    const int c = (i & 255) * 2;
    float2 v = *(const float2*)(src + (size_t)m * 512 + c);
    __half2 hp = __halves2half2(__float2half(v.x), __float2half(v.y));
    *(__half2*)(g_xcat + (size_t)m * KCAT + c) = hp;
}
__global__ __launch_bounds__(256) void conv_w(const float* __restrict__ Win,
                                              const float* __restrict__ Wg,
                                              const float* __restrict__ Wo) {
    const int w = blockIdx.y;
    const float* src = (w == 0) ? Win : (w == 1) ? Wg : Wo;
    __half* dst = (w == 0) ? g_wincat : (w == 1) ? g_wgcat : g_wocat;
    const int i = blockIdx.x * 256 + threadIdx.x;
    const int m = i >> 8;
    const int c = (i & 255) * 2;
    float2 v = *(const float2*)(src + (size_t)m * 512 + c);
    __half2 hp = __halves2half2(__float2half(v.x), __float2half(v.y));
    *(__half2*)(dst + (size_t)m * KCAT + c) = hp;
}

// ------------------------- ldmatrix + mma.sync fp16 GEMM (R8 mainloop) ----
// C[8192x512] = Acat[8192x512] · Wcat[512x512]^T  (fp16 in, fp32 acc)
// FUSED=1: blockIdx.z==0 -> g_u = x@W_in^T ; z==1 -> g_gate = sigmoid(..+b)
// FUSED=0: out = x + g_gate * (g_ycat@W_out^T)
#define BM 128
#define BN 128
#define BK 64
#define NCH (KCAT/BK)   // 8
#define SM_A 1024
#define SM_B 17408
#define GEMM_SMEM 33792

template<int FUSED01>
__global__ __launch_bounds__(256) void gemm_mma(
    const float* __restrict__ x_ext,     // x (FUSED=0 epilogue)
    float* __restrict__ Cout_ext,        // d_out (FUSED=0)
    const float* __restrict__ bgate) {   // b_gate (FUSED=1, z=1)
    __shared__ __align__(128) char smem[GEMM_SMEM];
    const uint32_t sb = smem_u32(smem);
    const int tid  = threadIdx.x;
    const int wid  = tid >> 5, lane = tid & 31;
    const int wm   = wid & 3;          // 4 m-blocks of 32 rows
    const int wn   = wid >> 2;         // 2 n-blocks of 64 cols
    const int m0 = blockIdx.x * BM;
    const int n0 = blockIdx.y * BN;
    const int bz = FUSED01 ? blockIdx.z : 0;   // 0: in-proj, 1: gate-proj

    const __half* Acat = FUSED01 ? g_xcat : g_ycat;
    const __half* Wcat = FUSED01 ? (bz ? g_wgcat : g_wincat) : g_wocat;

    if (FUSED01 && bz && tid < BN) ((float*)smem)[tid] = bgate[n0 + tid];

    // ---- global->reg prefetch geometry (4 x 16B per thread per tile)
    const int r_base = tid >> 3;            // 0..31
    const int cb_off = (tid & 7) * 16;      // byte col within 128B row
    uint32_t sw_st[4];
#pragma unroll
    for (int i = 0; i < 4; i++)
        sw_st[i] = sw128((uint32_t)((r_base + i * 32) * 128 + cb_off));
    const char* Abase = (const char*)(Acat + (size_t)(m0 + r_base) * KCAT) + cb_off;
    const char* Bbase = (const char*)(Wcat + (size_t)(n0 + r_base) * KCAT) + cb_off;
    const size_t rstep = (size_t)32 * KCAT * 2;

    uint4 aR[4], bR[4];
#pragma unroll
    for (int i = 0; i < 4; i++) {
        aR[i] = *(const uint4*)(Abase + i * rstep);
        bR[i] = *(const uint4*)(Bbase + i * rstep);
    }

    // ---- ldmatrix per-lane base offsets
    const int grp = lane >> 3;
    const int l7  = lane & 7;
    const uint32_t a_base = (uint32_t)((wm * 32 + ((grp & 1) ? 8 : 0) + l7) * 128
                                       + ((grp >> 1) ? 16 : 0));
    const uint32_t b_base = (uint32_t)((wn * 64 + ((grp >> 1) ? 8 : 0) + l7) * 128
                                       + ((grp & 1) ? 16 : 0));

    float acc[2][8][4];
#pragma unroll
    for (int mf = 0; mf < 2; mf++)
#pragma unroll
        for (int nf = 0; nf < 8; nf++)
#pragma unroll
            for (int q = 0; q < 4; q++) acc[mf][nf][q] = 0.0f;

    for (int kc = 0; kc < NCH; kc++) {
        if (kc) __syncthreads();
#pragma unroll
        for (int i = 0; i < 4; i++) {
            asm volatile("st.shared.v4.b32 [%0], {%1,%2,%3,%4};"
                         :: "r"(sb + SM_A + sw_st[i]),
                            "r"(aR[i].x), "r"(aR[i].y), "r"(aR[i].z), "r"(aR[i].w) : "memory");
            asm volatile("st.shared.v4.b32 [%0], {%1,%2,%3,%4};"
                         :: "r"(sb + SM_B + sw_st[i]),
                            "r"(bR[i].x), "r"(bR[i].y), "r"(bR[i].z), "r"(bR[i].w) : "memory");
        }
        __syncthreads();
        if (kc + 1 < NCH) {   // prefetch next chunk during compute
            const char* An = Abase + (size_t)(kc + 1) * (BK * 2);
            const char* Bn = Bbase + (size_t)(kc + 1) * (BK * 2);
#pragma unroll
            for (int i = 0; i < 4; i++) {
                aR[i] = *(const uint4*)(An + i * rstep);
                bR[i] = *(const uint4*)(Bn + i * rstep);
            }
        }
#pragma unroll
        for (int s = 0; s < 4; s++) {      // 4 k-steps of 16
            uint32_t af[2][4];
#pragma unroll
            for (int mf = 0; mf < 2; mf++)
                ldmx4(af[mf], sb + SM_A + sw128(a_base + mf * 2048 + s * 32));
            uint32_t bf[4][4];
#pragma unroll
            for (int nq = 0; nq < 4; nq++)
                ldmx4(bf[nq], sb + SM_B + sw128(b_base + nq * 2048 + s * 32));
#pragma unroll
            for (int mf = 0; mf < 2; mf++)
#pragma unroll
                for (int nq = 0; nq < 4; nq++) {
                    mma16816(acc[mf][nq * 2],     af[mf], bf[nq][0], bf[nq][1]);
                    mma16816(acc[mf][nq * 2 + 1], af[mf], bf[nq][2], bf[nq][3]);
                }
        }
    }

    // ---- epilogue
    const int rrow = lane >> 2;
    const int rcol = (lane & 3) * 2;
    float* Cbase = FUSED01 ? (bz ? g_gate : g_u) : Cout_ext;
#pragma unroll
    for (int mf = 0; mf < 2; mf++) {
        const int mrow = m0 + wm * 32 + mf * 16 + rrow;
#pragma unroll
        for (int nf = 0; nf < 8; nf++) {
            const int ncl = wn * 64 + nf * 8 + rcol;   // 0..127 within tile
            const int col = n0 + ncl;
            float2 v0 = make_float2(acc[mf][nf][0], acc[mf][nf][1]);
            float2 v1 = make_float2(acc[mf][nf][2], acc[mf][nf][3]);
            if (FUSED01) {
                if (bz) {
                    float2 bb = *(const float2*)((const float*)smem + ncl);
                    v0.x = __fdividef(1.0f, 1.0f + __expf(-(v0.x + bb.x)));
                    v0.y = __fdividef(1.0f, 1.0f + __expf(-(v0.y + bb.y)));
                    v1.x = __fdividef(1.0f, 1.0f + __expf(-(v1.x + bb.x)));
                    v1.y = __fdividef(1.0f, 1.0f + __expf(-(v1.y + bb.y)));
                }
            } else {
                float2 x0 = *(const float2*)(x_ext + (size_t)mrow * 512 + col);
                float2 g0 = *(const float2*)(g_gate + (size_t)mrow * 512 + col);
                float2 x1 = *(const float2*)(x_ext + (size_t)(mrow + 8) * 512 + col);
                float2 g1 = *(const float2*)(g_gate + (size_t)(mrow + 8) * 512 + col);
                v0.x = fmaf(g0.x, v0.x, x0.x); v0.y = fmaf(g0.y, v0.y, x0.y);
                v1.x = fmaf(g1.x, v1.x, x1.x); v1.y = fmaf(g1.y, v1.y, x1.y);
            }
            *(float2*)(Cbase + (size_t)mrow * 512 + col)       = v0;
            *(float2*)(Cbase + (size_t)(mrow + 8) * 512 + col) = v1;
        }
    }
}

// ------------------------- scan phase 1 (f32x2-packed) --------------------
__global__ __launch_bounds__(256) void scan_phase1() {
    __shared__ float Us[LCH][32];
    const int tid  = threadIdx.x;
    const int dblk = blockIdx.x, c = blockIdx.y, b = blockIdx.z;
    const int dd = tid >> 3, j = tid & 7;
    const int d  = dblk * 32 + dd;

    const float* u = g_u + (size_t)(b * SEQ + c * LCH) * 512 + dblk * 32;
    for (int r = tid >> 5; r < LCH; r += 8)
        Us[r][tid & 31] = u[(size_t)r * 512 + (tid & 31)];
    __syncthreads();

    const int nbase = j * 8;
    unsigned long long wr2[4], wi2[4], nwi2[4], sr2[4], si2[4];
    {
        const float4* p = (const float4*)(g_wr + d * STATE_N + nbase);
        float4 t0 = p[0], t1 = p[1];
        wr2[0] = pk2(t0.x, t0.y); wr2[1] = pk2(t0.z, t0.w);
        wr2[2] = pk2(t1.x, t1.y); wr2[3] = pk2(t1.z, t1.w);
        p = (const float4*)(g_wi + d * STATE_N + nbase);
        t0 = p[0]; t1 = p[1];
        wi2[0] = pk2(t0.x, t0.y); wi2[1] = pk2(t0.z, t0.w);
        wi2[2] = pk2(t1.x, t1.y); wi2[3] = pk2(t1.z, t1.w);
        nwi2[0] = pk2(-t0.x, -t0.y); nwi2[1] = pk2(-t0.z, -t0.w);
        nwi2[2] = pk2(-t1.x, -t1.y); nwi2[3] = pk2(-t1.z, -t1.w);
    }
#pragma unroll
    for (int p = 0; p < 4; p++) { sr2[p] = 0ull; si2[p] = 0ull; }

#pragma unroll 4
    for (int t = 0; t < LCH; t++) {
        float ut = Us[t][dd];
        unsigned long long u2 = pk2(ut, ut);
#pragma unroll
        for (int p = 0; p < 4; p++) {
            unsigned long long mm = mul2(wi2[p], sr2[p]);
            unsigned long long tt = ffma2(nwi2[p], si2[p], u2);
            sr2[p] = ffma2(wr2[p], sr2[p], tt);
            si2[p] = ffma2(wr2[p], si2[p], mm);
        }
    }
    float2* Sp = g_S + ((size_t)(c * BD + b * D_MODEL + d)) * STATE_N + nbase;
#pragma unroll
    for (int p = 0; p < 4; p++) {
        float2 a = up2(sr2[p]), bb = up2(si2[p]);
        Sp[2 * p]     = make_float2(a.x, bb.x);
        Sp[2 * p + 1] = make_float2(a.y, bb.y);
    }
}

// ------------------------- scan phase 2 -----------------------------------
__global__ __launch_bounds__(256) void scan_phase2() {
    const int i  = blockIdx.x * blockDim.x + threadIdx.x;
    const int bd = i >> 6;
    const int n  = i & 63;
    const int d  = bd & (D_MODEL - 1);
    const float wLr = g_wLr[d * STATE_N + n];
    const float wLi = g_wLi[d * STATE_N + n];
    float er = 0.0f, ei = 0.0f;
#pragma unroll
    for (int c = 0; c < NC; c++) {
        const size_t idx = ((size_t)c * BD + bd) * STATE_N + n;
        g_E[idx] = make_float2(er, ei);
        float2 s = g_S[idx];
        float nr = fmaf(wLr, er, fmaf(-wLi, ei, s.x));
        float ni = fmaf(wLr, ei, fmaf(wLi, er, s.y));
        er = nr; ei = ni;
    }
}

// ------------------------- scan phase 3: scan + fp16 y out ----------------
__global__ __launch_bounds__(256) void scan_phase3(const float* __restrict__ Dp) {
    __shared__ float Us[LCH][32];
    const int tid  = threadIdx.x;
    const int dblk = blockIdx.x, c = blockIdx.y, b = blockIdx.z;
    const int dd = tid >> 3, j = tid & 7;
    const int d  = dblk * 32 + dd;

    const float* u = g_u + (size_t)(b * SEQ + c * LCH) * 512 + dblk * 32;
    for (int r = tid >> 5; r < LCH; r += 8)
        Us[r][tid & 31] = u[(size_t)r * 512 + (tid & 31)];
    __syncthreads();

    const int nbase = j * 8;
    unsigned long long wr2[4], wi2[4], nwi2[4], cb2[4], sr2[4], si2[4];
    {
        const float4* p = (const float4*)(g_wr + d * STATE_N + nbase);
        float4 t0 = p[0], t1 = p[1];
        wr2[0] = pk2(t0.x, t0.y); wr2[1] = pk2(t0.z, t0.w);
        wr2[2] = pk2(t1.x, t1.y); wr2[3] = pk2(t1.z, t1.w);
        p = (const float4*)(g_wi + d * STATE_N + nbase);
        t0 = p[0]; t1 = p[1];
        wi2[0] = pk2(t0.x, t0.y); wi2[1] = pk2(t0.z, t0.w);
        wi2[2] = pk2(t1.x, t1.y); wi2[3] = pk2(t1.z, t1.w);
        nwi2[0] = pk2(-t0.x, -t0.y); nwi2[1] = pk2(-t0.z, -t0.w);
        nwi2[2] = pk2(-t1.x, -t1.y); nwi2[3] = pk2(-t1.z, -t1.w);
        p = (const float4*)(g_cb + d * STATE_N + nbase);
        t0 = p[0]; t1 = p[1];
        cb2[0] = pk2(t0.x, t0.y); cb2[1] = pk2(t0.z, t0.w);
        cb2[2] = pk2(t1.x, t1.y); cb2[3] = pk2(t1.z, t1.w);
    }
    {
        const float4* Ep = (const float4*)(g_E + ((size_t)(c * BD + b * D_MODEL + d)) * STATE_N + nbase);
#pragma unroll
        for (int p = 0; p < 4; p++) {
            float4 e = Ep[p];   // (sr0, si0, sr1, si1)
            sr2[p] = pk2(e.x, e.z);
            si2[p] = pk2(e.y, e.w);
        }
    }
    const float Dd = Dp[d];
    __half* ycat = g_ycat + (size_t)(b * SEQ + c * LCH) * KCAT + d;

#pragma unroll 4
    for (int t = 0; t < LCH; t++) {
        float ut = Us[t][dd];
        unsigned long long u2 = pk2(ut, ut);
        unsigned long long acc2 = 0ull;
#pragma unroll
        for (int p = 0; p < 4; p++) {
            unsigned long long mm = mul2(wi2[p], sr2[p]);
            unsigned long long tt = ffma2(nwi2[p], si2[p], u2);
            sr2[p] = ffma2(wr2[p], sr2[p], tt);
            si2[p] = ffma2(wr2[p], si2[p], mm);
            acc2   = ffma2(cb2[p], sr2[p], acc2);
        }
        float2 ap = up2(acc2);
        float accv = ap.x + ap.y;
        accv += __shfl_xor_sync(0xffffffffu, accv, 1, 8);
        accv += __shfl_xor_sync(0xffffffffu, accv, 2, 8);
        accv += __shfl_xor_sync(0xffffffffu, accv, 4, 8);
        if (j == 0) {
            float v = fmaf(Dd, ut, accv);
            ycat[(size_t)t * KCAT] = __float2half(v);
        }
    }
}

// ------------------------- launch ----------------------------------------
extern "C" void kernel_launch(void* const* d_in, const int* in_sizes, int n_in,
                              void* d_out, int out_size) {
    const float* x      = (const float*)d_in[0];
    const float* logAr  = (const float*)d_in[1];
    const float* Aim    = (const float*)d_in[2];
    const float* Bp_    = (const float*)d_in[3];
    const float* Cp_    = (const float*)d_in[4];
    const float* Dp_    = (const float*)d_in[5];
    const float* logdt  = (const float*)d_in[6];
    const float* W_in   = (const float*)d_in[7];
    const float* W_out  = (const float*)d_in[8];
    const float* W_gate = (const float*)d_in[9];
    const float* b_gate = (const float*)d_in[10];
    float* out = (float*)d_out;

    prep_kernel<<<(D_MODEL * STATE_N + 255) / 256, 256>>>(logAr, Aim, Bp_, Cp_, logdt);
    conv_x<<<M_ROWS, 256>>>(x);
    conv_w<<<dim3(D_MODEL, 3), 256>>>(W_in, W_gate, W_out);
    gemm_mma<1><<<dim3(M_ROWS / BM, D_MODEL / BN, 2), 256>>>(nullptr, nullptr, b_gate);
    scan_phase1<<<dim3(D_MODEL / 32, NC, BATCH), 256>>>();
    scan_phase2<<<(BD * STATE_N) / 256, 256>>>();
    scan_phase3<<<dim3(D_MODEL / 32, NC, BATCH), 256>>>(Dp_);
    gemm_mma<0><<<dim3(M_ROWS / BM, D_MODEL / BN, 1), 256>>>(x, out, nullptr);
}